// round 7
// baseline (speedup 1.0000x reference)
#include <cuda_runtime.h>
#include <cuda_bf16.h>
#include <cstdint>

// Problem constants
#define Bb 2
#define Ss 2048
#define Dd 256
#define Hh 8
#define NR (Bb*Ss)

// Scratch
__device__ float g_Q[Bb*Ss*Dd];
__device__ float g_K[Bb*Ss*Dd];
__device__ float g_V[Bb*Ss*Dd];
__device__ float g_q2[NR];
__device__ float g_k2[NR];
__device__ float g_d2[(size_t)Bb*Ss*Ss];   // 33.5 MB, causal part written
// pre-split transposed operands
__device__ float g_Qth[Bb*Dd*Ss], g_Qtl[Bb*Dd*Ss];     // tf32 hi/lo, [b][k][s]
__device__ float g_Kth[Bb*Dd*Ss], g_Ktl[Bb*Dd*Ss];     // tf32 hi/lo, [b][k][t]
__device__ uint32_t g_Vph[Bb*Dd*(Ss/2)], g_Vpl[Bb*Dd*(Ss/2)];  // bf16x2 pairs, [b][d][t/2]

// ===================== mma.sync helpers =====================
__device__ __forceinline__ uint32_t f2tf32(float f) {
    uint32_t r;
    asm("cvt.rna.tf32.f32 %0, %1;" : "=r"(r) : "f"(f));
    return r;
}
__device__ __forceinline__ void mma_tf32(float* c, const uint32_t* a, const uint32_t* b) {
    asm volatile(
        "mma.sync.aligned.m16n8k8.row.col.f32.tf32.tf32.f32 "
        "{%0,%1,%2,%3}, {%4,%5,%6,%7}, {%8,%9}, {%0,%1,%2,%3};"
        : "+f"(c[0]), "+f"(c[1]), "+f"(c[2]), "+f"(c[3])
        : "r"(a[0]), "r"(a[1]), "r"(a[2]), "r"(a[3]), "r"(b[0]), "r"(b[1]));
}
__device__ __forceinline__ void mma_bf16(float* c, const uint32_t* a, const uint32_t* b) {
    asm volatile(
        "mma.sync.aligned.m16n8k16.row.col.f32.bf16.bf16.f32 "
        "{%0,%1,%2,%3}, {%4,%5,%6,%7}, {%8,%9}, {%0,%1,%2,%3};"
        : "+f"(c[0]), "+f"(c[1]), "+f"(c[2]), "+f"(c[3])
        : "r"(a[0]), "r"(a[1]), "r"(a[2]), "r"(a[3]), "r"(b[0]), "r"(b[1]));
}
__device__ __forceinline__ uint32_t pack_bf16x2(float lo_val, float hi_val) {
    __nv_bfloat16 l = __float2bfloat16(lo_val);
    __nv_bfloat16 h = __float2bfloat16(hi_val);
    return (uint32_t)__bfloat16_as_ushort(l) | ((uint32_t)__bfloat16_as_ushort(h) << 16);
}

// ---------------------------------------------------------------------------
// Kernel 1: projections (SIMT fp32 SGEMM)
// ---------------------------------------------------------------------------
__global__ __launch_bounds__(256) void proj_kernel(
    const float* __restrict__ p, const float* __restrict__ e,
    const float* __restrict__ Wq, const float* __restrict__ Wk,
    const float* __restrict__ Wv)
{
    const int which = blockIdx.z;
    const float* src = (which == 2) ? e : p;
    const float* W   = (which == 0) ? Wq : (which == 1) ? Wk : Wv;
    float* dst       = (which == 0) ? g_Q : (which == 1) ? g_K : g_V;

    const int row0 = blockIdx.x * 64;
    const int col0 = blockIdx.y * 64;

    __shared__ float As[32][68];
    __shared__ float Bs[32][68];

    const int tid = threadIdx.x;
    const int tx = tid & 15;
    const int ty = tid >> 4;

    float acc[4][4] = {};
    for (int k0 = 0; k0 < Dd; k0 += 32) {
        for (int l = tid; l < 64*32; l += 256) {
            int k = l & 31, m = l >> 5;
            As[k][m] = src[(size_t)(row0 + m)*Dd + k0 + k];
        }
        for (int l = tid; l < 32*64; l += 256) {
            int n = l & 63, k = l >> 6;
            Bs[k][n] = W[(size_t)(k0 + k)*Dd + col0 + n];
        }
        __syncthreads();
        #pragma unroll
        for (int k = 0; k < 32; k++) {
            float4 a4 = *(const float4*)&As[k][ty*4];
            float4 b4 = *(const float4*)&Bs[k][tx*4];
            float a[4] = {a4.x, a4.y, a4.z, a4.w};
            float b[4] = {b4.x, b4.y, b4.z, b4.w};
            #pragma unroll
            for (int i = 0; i < 4; i++)
                #pragma unroll
                for (int j = 0; j < 4; j++)
                    acc[i][j] += a[i] * b[j];
        }
        __syncthreads();
    }
    #pragma unroll
    for (int i = 0; i < 4; i++) {
        float4 v = make_float4(acc[i][0], acc[i][1], acc[i][2], acc[i][3]);
        *(float4*)&dst[(size_t)(row0 + ty*4 + i)*Dd + col0 + tx*4] = v;
    }
}

// ---------------------------------------------------------------------------
// Kernel 2: row norms
// ---------------------------------------------------------------------------
__global__ __launch_bounds__(256) void norms_kernel()
{
    int warp = (blockIdx.x * blockDim.x + threadIdx.x) >> 5;
    int lane = threadIdx.x & 31;
    if (warp >= NR) return;
    const float* q = g_Q + (size_t)warp * Dd;
    const float* k = g_K + (size_t)warp * Dd;
    float sq = 0.f, sk = 0.f;
    for (int i = lane; i < Dd; i += 32) {
        float a = q[i]; sq += a * a;
        float b = k[i]; sk += b * b;
    }
    #pragma unroll
    for (int o = 16; o; o >>= 1) {
        sq += __shfl_xor_sync(0xFFFFFFFFu, sq, o);
        sk += __shfl_xor_sync(0xFFFFFFFFu, sk, o);
    }
    if (lane == 0) { g_q2[warp] = sq; g_k2[warp] = sk; }
}

// ---------------------------------------------------------------------------
// Kernel 3: operand pre-split + transpose.
// which=0: Q -> g_Qth/g_Qtl tf32 hi/lo [b][k][s]
// which=1: K -> g_Kth/g_Ktl tf32 hi/lo [b][k][t]
// which=2: V -> g_Vph/g_Vpl bf16x2 pairs [b][d][t/2]
// grid: (Ss/64, Bb, 3)  block: 256
// ---------------------------------------------------------------------------
__global__ __launch_bounds__(256) void convert_kernel()
{
    const int which = blockIdx.z;
    const int b = blockIdx.y;
    const int r0 = blockIdx.x * 64;             // s/t range
    const float* src = (which == 0) ? g_Q : (which == 1) ? g_K : g_V;

    __shared__ float ts[64][65];
    const int tid = threadIdx.x;

    for (int dt = 0; dt < 4; dt++) {            // d range [dt*64, dt*64+64)
        for (int l = tid; l < 64*64; l += 256) {
            int r = l >> 6, c = l & 63;
            ts[r][c] = src[((size_t)(b*Ss + r0 + r))*Dd + dt*64 + c];
        }
        __syncthreads();
        if (which < 2) {
            float* dh = (which == 0) ? g_Qth : g_Kth;
            float* dl = (which == 0) ? g_Qtl : g_Ktl;
            for (int l = tid; l < 64*64; l += 256) {
                int dr = l >> 6, sc = l & 63;
                float v = ts[sc][dr];
                float hf = __uint_as_float(f2tf32(v));
                float lf = __uint_as_float(f2tf32(v - hf));
                size_t oi = ((size_t)(b*Dd + dt*64 + dr))*Ss + r0 + sc;
                dh[oi] = hf;
                dl[oi] = lf;
            }
        } else {
            for (int l = tid; l < 64*32; l += 256) {
                int dr = l >> 5, pr = l & 31;
                float v0 = ts[2*pr][dr];
                float v1 = ts[2*pr + 1][dr];
                __nv_bfloat16 h0 = __float2bfloat16(v0);
                __nv_bfloat16 h1 = __float2bfloat16(v1);
                size_t oi = ((size_t)(b*Dd + dt*64 + dr))*(Ss/2) + r0/2 + pr;
                g_Vph[oi] = (uint32_t)__bfloat16_as_ushort(h0)
                          | ((uint32_t)__bfloat16_as_ushort(h1) << 16);
                g_Vpl[oi] = pack_bf16x2(v0 - __bfloat162float(h0),
                                        v1 - __bfloat162float(h1));
            }
        }
        __syncthreads();
    }
}

// ---------------------------------------------------------------------------
// Kernel 4: d2 via split-tf32 mma.sync, operands pre-split.
// Tile 128(s) x 64(t), K in slabs of 32. grid: (32, 16, Bb)  block: 256
// ---------------------------------------------------------------------------
#define QSTR 136   // (8cc + r) bank pattern: conflict-free frags; aligned float4 stage
#define KSTR 72
#define D2_SMEM ((2*32*QSTR + 2*32*KSTR)*4)   // 53248 B

__global__ __launch_bounds__(256, 2) void d2_mma_kernel()
{
    const int si = blockIdx.y, tt = blockIdx.x, b = blockIdx.z;
    if (tt > 2*si + 1) return;                 // fully above diagonal
    const int s0 = si*128, t0 = tt*64;

    extern __shared__ float sm[];
    float* Qh = sm;
    float* Ql = Qh + 32*QSTR;
    float* Kh = Ql + 32*QSTR;
    float* Kl = Kh + 32*KSTR;
    const uint32_t* uQh = (const uint32_t*)Qh;
    const uint32_t* uQl = (const uint32_t*)Ql;
    const uint32_t* uKh = (const uint32_t*)Kh;
    const uint32_t* uKl = (const uint32_t*)Kl;

    const int tid = threadIdx.x, lane = tid & 31, wid = tid >> 5;
    const int wm = wid & 3, wn = wid >> 2;      // 4x2 warp grid of 32x32

    const float* Qgh = g_Qth + (size_t)b*Dd*Ss;   // [k][s]
    const float* Qgl = g_Qtl + (size_t)b*Dd*Ss;
    const float* Kgh = g_Kth + (size_t)b*Dd*Ss;   // [k][t]
    const float* Kgl = g_Ktl + (size_t)b*Dd*Ss;

    float C[2][4][4] = {};

    for (int k0 = 0; k0 < Dd; k0 += 32) {
        __syncthreads();   // protect prior-iter frag reads
        // stage Q slab: 32 k-rows x 128 s, pure float4 copies
        for (int l = tid; l < 1024; l += 256) {
            int k = l >> 5, c = l & 31;
            size_t gi = (size_t)(k0 + k)*Ss + s0 + c*4;
            *(float4*)&Qh[k*QSTR + c*4] = *(const float4*)(Qgh + gi);
            *(float4*)&Ql[k*QSTR + c*4] = *(const float4*)(Qgl + gi);
        }
        // stage K slab: 32 k-rows x 64 t
        for (int l = tid; l < 512; l += 256) {
            int k = l >> 4, c = l & 15;
            size_t gi = (size_t)(k0 + k)*Ss + t0 + c*4;
            *(float4*)&Kh[k*KSTR + c*4] = *(const float4*)(Kgh + gi);
            *(float4*)&Kl[k*KSTR + c*4] = *(const float4*)(Kgl + gi);
        }
        __syncthreads();

        const int r = lane >> 2, cc = lane & 3;
        #pragma unroll
        for (int ks = 0; ks < 4; ks++) {
            uint32_t ah[2][4], al[2][4];
            #pragma unroll
            for (int mf = 0; mf < 2; mf++) {
                int mrow = wm*32 + mf*16 + r;
                int kc = ks*8 + cc;
                ah[mf][0] = uQh[kc*QSTR + mrow];
                ah[mf][1] = uQh[kc*QSTR + mrow + 8];
                ah[mf][2] = uQh[(kc+4)*QSTR + mrow];
                ah[mf][3] = uQh[(kc+4)*QSTR + mrow + 8];
                al[mf][0] = uQl[kc*QSTR + mrow];
                al[mf][1] = uQl[kc*QSTR + mrow + 8];
                al[mf][2] = uQl[(kc+4)*QSTR + mrow];
                al[mf][3] = uQl[(kc+4)*QSTR + mrow + 8];
            }
            uint32_t bh[4][2], bl[4][2];
            #pragma unroll
            for (int nf = 0; nf < 4; nf++) {
                int ncol = wn*32 + nf*8 + r;
                int kc = ks*8 + cc;
                bh[nf][0] = uKh[kc*KSTR + ncol];
                bh[nf][1] = uKh[(kc+4)*KSTR + ncol];
                bl[nf][0] = uKl[kc*KSTR + ncol];
                bl[nf][1] = uKl[(kc+4)*KSTR + ncol];
            }
            #pragma unroll
            for (int mf = 0; mf < 2; mf++)
                #pragma unroll
                for (int nf = 0; nf < 4; nf++) {
                    mma_tf32(C[mf][nf], ah[mf], bh[nf]);
                    mma_tf32(C[mf][nf], ah[mf], bl[nf]);
                    mma_tf32(C[mf][nf], al[mf], bh[nf]);
                }
        }
    }

    // epilogue: d2 = max(q2 + k2 - 2S, 0)
    float* d2b = g_d2 + (size_t)b*Ss*Ss;
    const int r = lane >> 2, q = lane & 3;
    #pragma unroll
    for (int mf = 0; mf < 2; mf++) {
        int s = s0 + wm*32 + mf*16 + r;
        float q2a = g_q2[b*Ss + s];
        float q2c = g_q2[b*Ss + s + 8];
        #pragma unroll
        for (int nf = 0; nf < 4; nf++) {
            int t = t0 + wn*32 + nf*8 + 2*q;
            float k2a = g_k2[b*Ss + t];
            float k2b = g_k2[b*Ss + t + 1];
            float2 v0 = make_float2(fmaxf(q2a + k2a - 2.0f*C[mf][nf][0], 0.0f),
                                    fmaxf(q2a + k2b - 2.0f*C[mf][nf][1], 0.0f));
            float2 v1 = make_float2(fmaxf(q2c + k2a - 2.0f*C[mf][nf][2], 0.0f),
                                    fmaxf(q2c + k2b - 2.0f*C[mf][nf][3], 0.0f));
            *(float2*)&d2b[(size_t)s*Ss + t]       = v0;
            *(float2*)&d2b[(size_t)(s+8)*Ss + t]   = v1;
        }
    }
}

// ---------------------------------------------------------------------------
// Kernel 5: attn via split-bf16 mma.sync, V pre-split/packed.
// Tile 128(s) x 64(d), chunk of 4 t-tiles; atomicAdd into leader head.
// grid: (16 s-tiles reversed, 8 chunks, Bb*4dchunk*Hh)  block: 256
// ---------------------------------------------------------------------------
#define PSTR 36
#define VSTR 36
#define AT_SMEM ((2*128*PSTR + 2*64*VSTR)*4)   // 55296 B

__global__ __launch_bounds__(256, 2) void attn_mma_kernel(
    const float* __restrict__ gamma, float* __restrict__ out)
{
    const int si = (int)gridDim.x - 1 - (int)blockIdx.x;   // biggest first
    const int chunk = blockIdx.y;
    const int n_t = 2*si + 2;
    if (4*chunk >= n_t) return;

    const int z = blockIdx.z;
    const int b = z >> 5, dch = (z >> 3) & 3, h = z & 7;
    const float gh = gamma[h];
    for (int h2 = 0; h2 < h; h2++)
        if (gamma[h2] == gh) return;                        // leader only
    const float coef = -1.0f / (-2.0f * gh + 1e-6f);

    const int s0 = si*128, d0 = dch*64;

    extern __shared__ uint32_t smu[];
    uint32_t* Psh = smu;                    // P hi bf16x2 [s][tpair]
    uint32_t* Psl = Psh + 128*PSTR;
    uint32_t* Vsh = Psl + 128*PSTR;         // V hi bf16x2 [d][tpair]
    uint32_t* Vsl = Vsh + 64*VSTR;

    const int tid = threadIdx.x, lane = tid & 31, wid = tid >> 5;
    const int wm = wid & 3, wn = wid >> 2;   // 4x2 warp grid of 32x32

    const float* d2b = g_d2 + (size_t)b*Ss*Ss;

    float C[2][4][4] = {};

    const int tt0 = 4*chunk, tt1 = min(tt0 + 4, n_t);
    for (int tt = tt0; tt < tt1; tt++) {
        const int t0 = tt*64;
        __syncthreads();    // protect previous-iter frag reads

        // stage P = exp(coef * d2), causal-masked, split bf16 hi/lo
        for (int l = tid; l < 4096; l += 256) {
            int r = l >> 5, pr = l & 31;
            int sg = s0 + r, tg = t0 + 2*pr;
            float2 dv = *(const float2*)(d2b + (size_t)sg*Ss + tg);
            float p0 = (tg     > sg) ? 0.0f : __expf(coef * dv.x);
            float p1 = (tg + 1 > sg) ? 0.0f : __expf(coef * dv.y);
            __nv_bfloat16 h0 = __float2bfloat16(p0);
            __nv_bfloat16 h1 = __float2bfloat16(p1);
            Psh[r*PSTR + pr] = (uint32_t)__bfloat16_as_ushort(h0)
                             | ((uint32_t)__bfloat16_as_ushort(h1) << 16);
            Psl[r*PSTR + pr] = pack_bf16x2(p0 - __bfloat162float(h0),
                                           p1 - __bfloat162float(h1));
        }
        // stage V tile: straight uint4 copies from pre-split [d][tpair]
        for (int l = tid; l < 512; l += 256) {
            int d = l >> 3, c = l & 7;
            size_t gi = ((size_t)(b*Dd + d0 + d))*(Ss/2) + t0/2 + c*4;
            *(uint4*)&Vsh[d*VSTR + c*4] = *(const uint4*)(g_Vph + gi);
            *(uint4*)&Vsl[d*VSTR + c*4] = *(const uint4*)(g_Vpl + gi);
        }
        __syncthreads();

        const int r = lane >> 2, cc = lane & 3;
        #pragma unroll
        for (int ks = 0; ks < 4; ks++) {
            uint32_t ah[2][4], al[2][4];
            #pragma unroll
            for (int mf = 0; mf < 2; mf++) {
                int srow = wm*32 + mf*16 + r;
                int pc = ks*8 + cc;
                ah[mf][0] = Psh[srow*PSTR + pc];
                ah[mf][1] = Psh[(srow+8)*PSTR + pc];
                ah[mf][2] = Psh[srow*PSTR + pc + 4];
                ah[mf][3] = Psh[(srow+8)*PSTR + pc + 4];
                al[mf][0] = Psl[srow*PSTR + pc];
                al[mf][1] = Psl[(srow+8)*PSTR + pc];
                al[mf][2] = Psl[srow*PSTR + pc + 4];
                al[mf][3] = Psl[(srow+8)*PSTR + pc + 4];
            }
            uint32_t bh[4][2], bl[4][2];
            #pragma unroll
            for (int nf = 0; nf < 4; nf++) {
                int dcol = wn*32 + nf*8 + r;
                int pc = ks*8 + cc;
                bh[nf][0] = Vsh[dcol*VSTR + pc];
                bh[nf][1] = Vsh[dcol*VSTR + pc + 4];
                bl[nf][0] = Vsl[dcol*VSTR + pc];
                bl[nf][1] = Vsl[dcol*VSTR + pc + 4];
            }
            #pragma unroll
            for (int mf = 0; mf < 2; mf++)
                #pragma unroll
                for (int nf = 0; nf < 4; nf++) {
                    mma_bf16(C[mf][nf], ah[mf], bh[nf]);
                    mma_bf16(C[mf][nf], ah[mf], bl[nf]);
                    mma_bf16(C[mf][nf], al[mf], bh[nf]);
                }
        }
    }

    // epilogue: accumulate into leader head's output slice
    float* o = out + ((size_t)(b*Hh + h)*Ss)*Dd;
    const int r = lane >> 2, q = lane & 3;
    #pragma unroll
    for (int mf = 0; mf < 2; mf++) {
        int s = s0 + wm*32 + mf*16 + r;
        #pragma unroll
        for (int nf = 0; nf < 4; nf++) {
            int d = d0 + wn*32 + nf*8 + 2*q;
            atomicAdd(&o[(size_t)s*Dd + d],         C[mf][nf][0]);
            atomicAdd(&o[(size_t)s*Dd + d + 1],     C[mf][nf][1]);
            atomicAdd(&o[(size_t)(s+8)*Dd + d],     C[mf][nf][2]);
            atomicAdd(&o[(size_t)(s+8)*Dd + d + 1], C[mf][nf][3]);
        }
    }
}

// ---------------------------------------------------------------------------
// Kernel 6: broadcast leader head output to duplicate-gamma heads.
// ---------------------------------------------------------------------------
__global__ __launch_bounds__(256) void bcast_kernel(
    const float* __restrict__ gamma, float* __restrict__ out)
{
    const int h = blockIdx.y, b = blockIdx.z;
    const float gh = gamma[h];
    int leader = h;
    for (int h2 = 0; h2 < h; h2++)
        if (gamma[h2] == gh) { leader = h2; break; }
    if (leader == h) return;

    size_t idx = ((size_t)blockIdx.x * 256 + threadIdx.x) * 4;
    const float4 v = *(const float4*)&out[((size_t)(b*Hh + leader)*Ss)*Dd + idx];
    *(float4*)&out[((size_t)(b*Hh + h)*Ss)*Dd + idx] = v;
}

// ---------------------------------------------------------------------------
extern "C" void kernel_launch(void* const* d_in, const int* in_sizes, int n_in,
                              void* d_out, int out_size)
{
    // metadata order: x, e, p, W_q, W_k, W_v, gamma
    const float* e     = (const float*)d_in[1];
    const float* p     = (const float*)d_in[2];
    const float* Wq    = (const float*)d_in[3];
    const float* Wk    = (const float*)d_in[4];
    const float* Wv    = (const float*)d_in[5];
    const float* gamma = (const float*)d_in[6];
    float* out = (float*)d_out;

    static bool attr_set = false;
    if (!attr_set) {
        cudaFuncSetAttribute(d2_mma_kernel,
                             cudaFuncAttributeMaxDynamicSharedMemorySize, D2_SMEM);
        cudaFuncSetAttribute(attn_mma_kernel,
                             cudaFuncAttributeMaxDynamicSharedMemorySize, AT_SMEM);
        attr_set = true;
    }

    dim3 gproj(NR/64, Dd/64, 3);
    proj_kernel<<<gproj, 256>>>(p, e, Wq, Wk, Wv);

    norms_kernel<<<(NR*32)/256, 256>>>();

    dim3 gcv(Ss/64, Bb, 3);
    convert_kernel<<<gcv, 256>>>();

    dim3 gd2(32, 16, Bb);
    d2_mma_kernel<<<gd2, 256, D2_SMEM>>>();

    cudaMemsetAsync(d_out, 0, (size_t)out_size * sizeof(float));

    dim3 gattn(16, 8, Bb * 4 * Hh);
    attn_mma_kernel<<<gattn, 256, AT_SMEM>>>(gamma, out);

    dim3 gb((Ss*Dd)/1024, Hh, Bb);
    bcast_kernel<<<gb, 256>>>(gamma, out);
}

// round 8
// speedup vs baseline: 1.1908x; 1.1908x over previous
#include <cuda_runtime.h>
#include <cuda_bf16.h>
#include <cstdint>

// Problem constants
#define Bb 2
#define Ss 2048
#define Dd 256
#define Hh 8
#define NR (Bb*Ss)

// Scratch
__device__ float g_Q[Bb*Ss*Dd];
__device__ float g_K[Bb*Ss*Dd];
__device__ float g_V[Bb*Ss*Dd];
__device__ float g_q2[NR];
__device__ float g_k2[NR];
// pre-split transposed operands
__device__ float g_Qth[Bb*Dd*Ss], g_Qtl[Bb*Dd*Ss];     // tf32 hi/lo, [b][k][s]
__device__ float g_Kth[Bb*Dd*Ss], g_Ktl[Bb*Dd*Ss];     // tf32 hi/lo, [b][k][t]
__device__ uint32_t g_Vph[Bb*Dd*(Ss/2)], g_Vpl[Bb*Dd*(Ss/2)];  // bf16x2 pairs, [b][d][t/2]

// ===================== mma.sync helpers =====================
__device__ __forceinline__ uint32_t f2tf32(float f) {
    uint32_t r;
    asm("cvt.rna.tf32.f32 %0, %1;" : "=r"(r) : "f"(f));
    return r;
}
__device__ __forceinline__ void mma_tf32(float* c, const uint32_t* a, const uint32_t* b) {
    asm volatile(
        "mma.sync.aligned.m16n8k8.row.col.f32.tf32.tf32.f32 "
        "{%0,%1,%2,%3}, {%4,%5,%6,%7}, {%8,%9}, {%0,%1,%2,%3};"
        : "+f"(c[0]), "+f"(c[1]), "+f"(c[2]), "+f"(c[3])
        : "r"(a[0]), "r"(a[1]), "r"(a[2]), "r"(a[3]), "r"(b[0]), "r"(b[1]));
}
__device__ __forceinline__ void mma_bf16(float* c, const uint32_t* a, const uint32_t* b) {
    asm volatile(
        "mma.sync.aligned.m16n8k16.row.col.f32.bf16.bf16.f32 "
        "{%0,%1,%2,%3}, {%4,%5,%6,%7}, {%8,%9}, {%0,%1,%2,%3};"
        : "+f"(c[0]), "+f"(c[1]), "+f"(c[2]), "+f"(c[3])
        : "r"(a[0]), "r"(a[1]), "r"(a[2]), "r"(a[3]), "r"(b[0]), "r"(b[1]));
}
__device__ __forceinline__ uint32_t pack_bf16x2(float lo_val, float hi_val) {
    __nv_bfloat16 l = __float2bfloat16(lo_val);
    __nv_bfloat16 h = __float2bfloat16(hi_val);
    return (uint32_t)__bfloat16_as_ushort(l) | ((uint32_t)__bfloat16_as_ushort(h) << 16);
}

// ---------------------------------------------------------------------------
// Kernel 1: projections (SIMT fp32 SGEMM)
// ---------------------------------------------------------------------------
__global__ __launch_bounds__(256) void proj_kernel(
    const float* __restrict__ p, const float* __restrict__ e,
    const float* __restrict__ Wq, const float* __restrict__ Wk,
    const float* __restrict__ Wv)
{
    const int which = blockIdx.z;
    const float* src = (which == 2) ? e : p;
    const float* W   = (which == 0) ? Wq : (which == 1) ? Wk : Wv;
    float* dst       = (which == 0) ? g_Q : (which == 1) ? g_K : g_V;

    const int row0 = blockIdx.x * 64;
    const int col0 = blockIdx.y * 64;

    __shared__ float As[32][68];
    __shared__ float Bs[32][68];

    const int tid = threadIdx.x;
    const int tx = tid & 15;
    const int ty = tid >> 4;

    float acc[4][4] = {};
    for (int k0 = 0; k0 < Dd; k0 += 32) {
        for (int l = tid; l < 64*32; l += 256) {
            int k = l & 31, m = l >> 5;
            As[k][m] = src[(size_t)(row0 + m)*Dd + k0 + k];
        }
        for (int l = tid; l < 32*64; l += 256) {
            int n = l & 63, k = l >> 6;
            Bs[k][n] = W[(size_t)(k0 + k)*Dd + col0 + n];
        }
        __syncthreads();
        #pragma unroll
        for (int k = 0; k < 32; k++) {
            float4 a4 = *(const float4*)&As[k][ty*4];
            float4 b4 = *(const float4*)&Bs[k][tx*4];
            float a[4] = {a4.x, a4.y, a4.z, a4.w};
            float b[4] = {b4.x, b4.y, b4.z, b4.w};
            #pragma unroll
            for (int i = 0; i < 4; i++)
                #pragma unroll
                for (int j = 0; j < 4; j++)
                    acc[i][j] += a[i] * b[j];
        }
        __syncthreads();
    }
    #pragma unroll
    for (int i = 0; i < 4; i++) {
        float4 v = make_float4(acc[i][0], acc[i][1], acc[i][2], acc[i][3]);
        *(float4*)&dst[(size_t)(row0 + ty*4 + i)*Dd + col0 + tx*4] = v;
    }
}

// ---------------------------------------------------------------------------
// Kernel 2: row norms
// ---------------------------------------------------------------------------
__global__ __launch_bounds__(256) void norms_kernel()
{
    int warp = (blockIdx.x * blockDim.x + threadIdx.x) >> 5;
    int lane = threadIdx.x & 31;
    if (warp >= NR) return;
    const float* q = g_Q + (size_t)warp * Dd;
    const float* k = g_K + (size_t)warp * Dd;
    float sq = 0.f, sk = 0.f;
    for (int i = lane; i < Dd; i += 32) {
        float a = q[i]; sq += a * a;
        float b = k[i]; sk += b * b;
    }
    #pragma unroll
    for (int o = 16; o; o >>= 1) {
        sq += __shfl_xor_sync(0xFFFFFFFFu, sq, o);
        sk += __shfl_xor_sync(0xFFFFFFFFu, sk, o);
    }
    if (lane == 0) { g_q2[warp] = sq; g_k2[warp] = sk; }
}

// ---------------------------------------------------------------------------
// Kernel 3: operand pre-split + transpose (Q,K -> tf32 hi/lo [b][k][s];
// V -> bf16x2 pairs [b][d][t/2]).  grid: (Ss/64, Bb, 3)  block: 256
// ---------------------------------------------------------------------------
__global__ __launch_bounds__(256) void convert_kernel()
{
    const int which = blockIdx.z;
    const int b = blockIdx.y;
    const int r0 = blockIdx.x * 64;
    const float* src = (which == 0) ? g_Q : (which == 1) ? g_K : g_V;

    __shared__ float ts[64][65];
    const int tid = threadIdx.x;

    for (int dt = 0; dt < 4; dt++) {
        for (int l = tid; l < 64*64; l += 256) {
            int r = l >> 6, c = l & 63;
            ts[r][c] = src[((size_t)(b*Ss + r0 + r))*Dd + dt*64 + c];
        }
        __syncthreads();
        if (which < 2) {
            float* dh = (which == 0) ? g_Qth : g_Kth;
            float* dl = (which == 0) ? g_Qtl : g_Ktl;
            for (int l = tid; l < 64*64; l += 256) {
                int dr = l >> 6, sc = l & 63;
                float v = ts[sc][dr];
                float hf = __uint_as_float(f2tf32(v));
                float lf = __uint_as_float(f2tf32(v - hf));
                size_t oi = ((size_t)(b*Dd + dt*64 + dr))*Ss + r0 + sc;
                dh[oi] = hf;
                dl[oi] = lf;
            }
        } else {
            for (int l = tid; l < 64*32; l += 256) {
                int dr = l >> 5, pr = l & 31;
                float v0 = ts[2*pr][dr];
                float v1 = ts[2*pr + 1][dr];
                __nv_bfloat16 h0 = __float2bfloat16(v0);
                __nv_bfloat16 h1 = __float2bfloat16(v1);
                size_t oi = ((size_t)(b*Dd + dt*64 + dr))*(Ss/2) + r0/2 + pr;
                g_Vph[oi] = (uint32_t)__bfloat16_as_ushort(h0)
                          | ((uint32_t)__bfloat16_as_ushort(h1) << 16);
                g_Vpl[oi] = pack_bf16x2(v0 - __bfloat162float(h0),
                                        v1 - __bfloat162float(h1));
            }
        }
        __syncthreads();
    }
}

// ---------------------------------------------------------------------------
// Kernel 4 (fused): per (b, leader-h, s-tile 128, chunk of 2 t-tiles):
//   Phase A: S = QK^T (split-tf32), epilogue -> P = exp(coef*d2) masked,
//            split-bf16 in SMEM (both tiles).
//   Phase B: for each 64-wide d-chunk: OUT += P @ V^T (split-bf16, both
//            tiles), atomicAdd to leader head.
// grid: (16 s-tiles, 16 chunks, Bb*Hh)   block: 256 (4x2 warps of 32x32)
// ---------------------------------------------------------------------------
#define QSTR 136
#define KSTR 72
#define PSTR 36
#define VSTR 36
// SMEM layout (uint32 units):
//   Ph0=0  Pl0=4608  Ph1=9216  Pl1=13824          (P tiles, 73728 B)
//   U=18432: union of {QK slabs: Qh 2176, Ql 2176, K 4x1152}
//            and     {V: V0h 2304, V0l, V1h, V1l}  (36864 B)
#define U_OFF 18432
#define FUSED_SMEM ((18432 + 9216)*4)   // 110592 B

__global__ __launch_bounds__(256, 2) void fused_attn_kernel(
    const float* __restrict__ gamma, float* __restrict__ out)
{
    const int si = blockIdx.x;
    const int chunk = blockIdx.y;
    if (chunk > si) return;                    // chunks = si+1, all equal work
    const int z = blockIdx.z;
    const int b = z >> 3, h = z & 7;
    const float gh = gamma[h];
    for (int h2 = 0; h2 < h; h2++)
        if (gamma[h2] == gh) return;           // leader only
    const float coef = -1.0f / (-2.0f * gh + 1e-6f);

    const int s0 = si * 128;
    const int t0a = chunk * 128;               // tile 0
    const int t0b = t0a + 64;                  // tile 1

    extern __shared__ uint32_t smu[];
    uint32_t* Ph[2] = { smu,          smu + 9216 };
    uint32_t* Pl[2] = { smu + 4608,   smu + 13824 };
    // slab view
    float* Qh  = (float*)(smu + U_OFF);
    float* Ql  = Qh + 2176;
    float* Kh0 = Ql + 2176;
    float* Kl0 = Kh0 + 1152;
    float* Kh1 = Kl0 + 1152;
    float* Kl1 = Kh1 + 1152;
    const uint32_t* uQh = (const uint32_t*)Qh;
    const uint32_t* uQl = (const uint32_t*)Ql;
    // V view (same region)
    uint32_t* Vh[2] = { smu + U_OFF,        smu + U_OFF + 4608 };
    uint32_t* Vl[2] = { smu + U_OFF + 2304, smu + U_OFF + 6912 };

    const int tid = threadIdx.x, lane = tid & 31, wid = tid >> 5;
    const int wm = wid & 3, wn = wid >> 2;     // 4(s) x 2(t/d) warp grid
    const int r = lane >> 2, cc = lane & 3;

    const float* Qgh = g_Qth + (size_t)b*Dd*Ss;
    const float* Qgl = g_Qtl + (size_t)b*Dd*Ss;
    const float* Kgh = g_Kth + (size_t)b*Dd*Ss;
    const float* Kgl = g_Ktl + (size_t)b*Dd*Ss;

    // ---------------- Phase A: S = Q K^T for both tiles ----------------
    float C0[2][4][4] = {}, C1[2][4][4] = {};

    for (int k0 = 0; k0 < Dd; k0 += 16) {
        __syncthreads();
        // stage Q slab 16k x 128s (hi/lo)
        for (int l = tid; l < 512; l += 256) {
            int k = l >> 5, c = l & 31;
            size_t gi = (size_t)(k0 + k)*Ss + s0 + c*4;
            *(float4*)&Qh[k*QSTR + c*4] = *(const float4*)(Qgh + gi);
            *(float4*)&Ql[k*QSTR + c*4] = *(const float4*)(Qgl + gi);
        }
        // stage K slabs 16k x 64t for both tiles (hi/lo)
        for (int l = tid; l < 256; l += 256) {
            int k = l >> 4, c = l & 15;
            size_t gia = (size_t)(k0 + k)*Ss + t0a + c*4;
            size_t gib = (size_t)(k0 + k)*Ss + t0b + c*4;
            *(float4*)&Kh0[k*KSTR + c*4] = *(const float4*)(Kgh + gia);
            *(float4*)&Kl0[k*KSTR + c*4] = *(const float4*)(Kgl + gia);
            *(float4*)&Kh1[k*KSTR + c*4] = *(const float4*)(Kgh + gib);
            *(float4*)&Kl1[k*KSTR + c*4] = *(const float4*)(Kgl + gib);
        }
        __syncthreads();

        #pragma unroll
        for (int ks = 0; ks < 2; ks++) {
            const int kc = ks*8 + cc;
            uint32_t ah[2][4], al[2][4];
            #pragma unroll
            for (int mf = 0; mf < 2; mf++) {
                int mrow = wm*32 + mf*16 + r;
                ah[mf][0] = uQh[kc*QSTR + mrow];
                ah[mf][1] = uQh[kc*QSTR + mrow + 8];
                ah[mf][2] = uQh[(kc+4)*QSTR + mrow];
                ah[mf][3] = uQh[(kc+4)*QSTR + mrow + 8];
                al[mf][0] = uQl[kc*QSTR + mrow];
                al[mf][1] = uQl[kc*QSTR + mrow + 8];
                al[mf][2] = uQl[(kc+4)*QSTR + mrow];
                al[mf][3] = uQl[(kc+4)*QSTR + mrow + 8];
            }
            {   // tile 0
                const uint32_t* uKh = (const uint32_t*)Kh0;
                const uint32_t* uKl = (const uint32_t*)Kl0;
                uint32_t bh[4][2], bl[4][2];
                #pragma unroll
                for (int nf = 0; nf < 4; nf++) {
                    int ncol = wn*32 + nf*8 + r;
                    bh[nf][0] = uKh[kc*KSTR + ncol];
                    bh[nf][1] = uKh[(kc+4)*KSTR + ncol];
                    bl[nf][0] = uKl[kc*KSTR + ncol];
                    bl[nf][1] = uKl[(kc+4)*KSTR + ncol];
                }
                #pragma unroll
                for (int mf = 0; mf < 2; mf++)
                    #pragma unroll
                    for (int nf = 0; nf < 4; nf++) {
                        mma_tf32(C0[mf][nf], ah[mf], bh[nf]);
                        mma_tf32(C0[mf][nf], ah[mf], bl[nf]);
                        mma_tf32(C0[mf][nf], al[mf], bh[nf]);
                    }
            }
            {   // tile 1
                const uint32_t* uKh = (const uint32_t*)Kh1;
                const uint32_t* uKl = (const uint32_t*)Kl1;
                uint32_t bh[4][2], bl[4][2];
                #pragma unroll
                for (int nf = 0; nf < 4; nf++) {
                    int ncol = wn*32 + nf*8 + r;
                    bh[nf][0] = uKh[kc*KSTR + ncol];
                    bh[nf][1] = uKh[(kc+4)*KSTR + ncol];
                    bl[nf][0] = uKl[kc*KSTR + ncol];
                    bl[nf][1] = uKl[(kc+4)*KSTR + ncol];
                }
                #pragma unroll
                for (int mf = 0; mf < 2; mf++)
                    #pragma unroll
                    for (int nf = 0; nf < 4; nf++) {
                        mma_tf32(C1[mf][nf], ah[mf], bh[nf]);
                        mma_tf32(C1[mf][nf], ah[mf], bl[nf]);
                        mma_tf32(C1[mf][nf], al[mf], bh[nf]);
                    }
            }
        }
    }

    // ---------------- Epilogue A: P = exp(coef * d2), split bf16 --------
    #pragma unroll
    for (int tl = 0; tl < 2; tl++) {
        const int t0 = tl ? t0b : t0a;
        float (*C)[4][4] = tl ? C1 : C0;
        #pragma unroll
        for (int mf = 0; mf < 2; mf++) {
            int sl = wm*32 + mf*16 + r;
            int sg = s0 + sl;
            float q2a = g_q2[b*Ss + sg];
            float q2c = g_q2[b*Ss + sg + 8];
            #pragma unroll
            for (int nf = 0; nf < 4; nf++) {
                int tg = t0 + wn*32 + nf*8 + 2*cc;
                float k2a = g_k2[b*Ss + tg];
                float k2b = g_k2[b*Ss + tg + 1];
                float p00 = (tg     > sg) ? 0.0f : __expf(coef * fmaxf(q2a + k2a - 2.0f*C[mf][nf][0], 0.0f));
                float p01 = (tg + 1 > sg) ? 0.0f : __expf(coef * fmaxf(q2a + k2b - 2.0f*C[mf][nf][1], 0.0f));
                float p10 = (tg     > sg + 8) ? 0.0f : __expf(coef * fmaxf(q2c + k2a - 2.0f*C[mf][nf][2], 0.0f));
                float p11 = (tg + 1 > sg + 8) ? 0.0f : __expf(coef * fmaxf(q2c + k2b - 2.0f*C[mf][nf][3], 0.0f));
                int pidx = wn*16 + nf*4 + cc;
                __nv_bfloat16 h00 = __float2bfloat16(p00);
                __nv_bfloat16 h01 = __float2bfloat16(p01);
                __nv_bfloat16 h10 = __float2bfloat16(p10);
                __nv_bfloat16 h11 = __float2bfloat16(p11);
                Ph[tl][sl*PSTR + pidx] = (uint32_t)__bfloat16_as_ushort(h00)
                                       | ((uint32_t)__bfloat16_as_ushort(h01) << 16);
                Ph[tl][(sl+8)*PSTR + pidx] = (uint32_t)__bfloat16_as_ushort(h10)
                                           | ((uint32_t)__bfloat16_as_ushort(h11) << 16);
                Pl[tl][sl*PSTR + pidx] = pack_bf16x2(p00 - __bfloat162float(h00),
                                                     p01 - __bfloat162float(h01));
                Pl[tl][(sl+8)*PSTR + pidx] = pack_bf16x2(p10 - __bfloat162float(h10),
                                                         p11 - __bfloat162float(h11));
            }
        }
    }
    __syncthreads();   // P visible to all; slab region free for V

    // ---------------- Phase B: OUT += P @ V^T per d-chunk ----------------
    float* o = out + ((size_t)(b*Hh + h)*Ss)*Dd;

    for (int dch = 0; dch < 4; dch++) {
        // stage V tiles for this d-chunk (straight uint4 copies)
        for (int l = tid; l < 512; l += 256) {
            int d = l >> 3, c = l & 7;
            size_t gia = ((size_t)(b*Dd + dch*64 + d))*(Ss/2) + t0a/2 + c*4;
            size_t gib = ((size_t)(b*Dd + dch*64 + d))*(Ss/2) + t0b/2 + c*4;
            *(uint4*)&Vh[0][d*VSTR + c*4] = *(const uint4*)(g_Vph + gia);
            *(uint4*)&Vl[0][d*VSTR + c*4] = *(const uint4*)(g_Vpl + gia);
            *(uint4*)&Vh[1][d*VSTR + c*4] = *(const uint4*)(g_Vph + gib);
            *(uint4*)&Vl[1][d*VSTR + c*4] = *(const uint4*)(g_Vpl + gib);
        }
        __syncthreads();

        float C[2][4][4] = {};
        #pragma unroll
        for (int tl = 0; tl < 2; tl++) {
            #pragma unroll
            for (int ks = 0; ks < 4; ks++) {
                const int pc = ks*8 + cc;
                uint32_t ah[2][4], al[2][4];
                #pragma unroll
                for (int mf = 0; mf < 2; mf++) {
                    int srow = wm*32 + mf*16 + r;
                    ah[mf][0] = Ph[tl][srow*PSTR + pc];
                    ah[mf][1] = Ph[tl][(srow+8)*PSTR + pc];
                    ah[mf][2] = Ph[tl][srow*PSTR + pc + 4];
                    ah[mf][3] = Ph[tl][(srow+8)*PSTR + pc + 4];
                    al[mf][0] = Pl[tl][srow*PSTR + pc];
                    al[mf][1] = Pl[tl][(srow+8)*PSTR + pc];
                    al[mf][2] = Pl[tl][srow*PSTR + pc + 4];
                    al[mf][3] = Pl[tl][(srow+8)*PSTR + pc + 4];
                }
                uint32_t bh[4][2], bl[4][2];
                #pragma unroll
                for (int nf = 0; nf < 4; nf++) {
                    int dcol = wn*32 + nf*8 + r;
                    bh[nf][0] = Vh[tl][dcol*VSTR + pc];
                    bh[nf][1] = Vh[tl][dcol*VSTR + pc + 4];
                    bl[nf][0] = Vl[tl][dcol*VSTR + pc];
                    bl[nf][1] = Vl[tl][dcol*VSTR + pc + 4];
                }
                #pragma unroll
                for (int mf = 0; mf < 2; mf++)
                    #pragma unroll
                    for (int nf = 0; nf < 4; nf++) {
                        mma_bf16(C[mf][nf], ah[mf], bh[nf]);
                        mma_bf16(C[mf][nf], ah[mf], bl[nf]);
                        mma_bf16(C[mf][nf], al[mf], bh[nf]);
                    }
            }
        }
        // epilogue: accumulate to leader head output
        #pragma unroll
        for (int mf = 0; mf < 2; mf++) {
            int s = s0 + wm*32 + mf*16 + r;
            #pragma unroll
            for (int nf = 0; nf < 4; nf++) {
                int d = dch*64 + wn*32 + nf*8 + 2*cc;
                atomicAdd(&o[(size_t)s*Dd + d],         C[mf][nf][0]);
                atomicAdd(&o[(size_t)s*Dd + d + 1],     C[mf][nf][1]);
                atomicAdd(&o[(size_t)(s+8)*Dd + d],     C[mf][nf][2]);
                atomicAdd(&o[(size_t)(s+8)*Dd + d + 1], C[mf][nf][3]);
            }
        }
        __syncthreads();   // before overwriting V
    }
}

// ---------------------------------------------------------------------------
// Kernel 5: broadcast leader head output to duplicate-gamma heads.
// ---------------------------------------------------------------------------
__global__ __launch_bounds__(256) void bcast_kernel(
    const float* __restrict__ gamma, float* __restrict__ out)
{
    const int h = blockIdx.y, b = blockIdx.z;
    const float gh = gamma[h];
    int leader = h;
    for (int h2 = 0; h2 < h; h2++)
        if (gamma[h2] == gh) { leader = h2; break; }
    if (leader == h) return;

    size_t idx = ((size_t)blockIdx.x * 256 + threadIdx.x) * 4;
    const float4 v = *(const float4*)&out[((size_t)(b*Hh + leader)*Ss)*Dd + idx];
    *(float4*)&out[((size_t)(b*Hh + h)*Ss)*Dd + idx] = v;
}

// ---------------------------------------------------------------------------
extern "C" void kernel_launch(void* const* d_in, const int* in_sizes, int n_in,
                              void* d_out, int out_size)
{
    // metadata order: x, e, p, W_q, W_k, W_v, gamma
    const float* e     = (const float*)d_in[1];
    const float* p     = (const float*)d_in[2];
    const float* Wq    = (const float*)d_in[3];
    const float* Wk    = (const float*)d_in[4];
    const float* Wv    = (const float*)d_in[5];
    const float* gamma = (const float*)d_in[6];
    float* out = (float*)d_out;

    static bool attr_set = false;
    if (!attr_set) {
        cudaFuncSetAttribute(fused_attn_kernel,
                             cudaFuncAttributeMaxDynamicSharedMemorySize, FUSED_SMEM);
        attr_set = true;
    }

    dim3 gproj(NR/64, Dd/64, 3);
    proj_kernel<<<gproj, 256>>>(p, e, Wq, Wk, Wv);

    norms_kernel<<<(NR*32)/256, 256>>>();

    dim3 gcv(Ss/64, Bb, 3);
    convert_kernel<<<gcv, 256>>>();

    cudaMemsetAsync(d_out, 0, (size_t)out_size * sizeof(float));

    dim3 gf(16, 16, Bb*Hh);
    fused_attn_kernel<<<gf, 256, FUSED_SMEM>>>(gamma, out);

    dim3 gb((Ss*Dd)/1024, Hh, Bb);
    bcast_kernel<<<gb, 256>>>(gamma, out);
}

// round 9
// speedup vs baseline: 1.3122x; 1.1019x over previous
#include <cuda_runtime.h>
#include <cuda_bf16.h>
#include <cstdint>

// Problem constants
#define Bb 2
#define Ss 2048
#define Dd 256
#define Hh 8
#define NR (Bb*Ss)

// Scratch: pre-split transposed operands + norms
__device__ __align__(16) float g_Qth[Bb*Dd*Ss], g_Qtl[Bb*Dd*Ss];   // tf32 hi/lo, [b][k][s]
__device__ __align__(16) float g_Kth[Bb*Dd*Ss], g_Ktl[Bb*Dd*Ss];   // tf32 hi/lo, [b][k][t]
__device__ __align__(16) uint32_t g_Vph[Bb*Dd*(Ss/2)], g_Vpl[Bb*Dd*(Ss/2)]; // bf16x2 pairs, [b][d][t/2]
__device__ float g_q2[NR];
__device__ float g_k2[NR];

// ===================== helpers =====================
__device__ __forceinline__ uint32_t f2tf32(float f) {
    uint32_t r;
    asm("cvt.rna.tf32.f32 %0, %1;" : "=r"(r) : "f"(f));
    return r;
}
__device__ __forceinline__ void mma_tf32(float* c, const uint32_t* a, const uint32_t* b) {
    asm volatile(
        "mma.sync.aligned.m16n8k8.row.col.f32.tf32.tf32.f32 "
        "{%0,%1,%2,%3}, {%4,%5,%6,%7}, {%8,%9}, {%0,%1,%2,%3};"
        : "+f"(c[0]), "+f"(c[1]), "+f"(c[2]), "+f"(c[3])
        : "r"(a[0]), "r"(a[1]), "r"(a[2]), "r"(a[3]), "r"(b[0]), "r"(b[1]));
}
__device__ __forceinline__ void mma_bf16(float* c, const uint32_t* a, const uint32_t* b) {
    asm volatile(
        "mma.sync.aligned.m16n8k16.row.col.f32.bf16.bf16.f32 "
        "{%0,%1,%2,%3}, {%4,%5,%6,%7}, {%8,%9}, {%0,%1,%2,%3};"
        : "+f"(c[0]), "+f"(c[1]), "+f"(c[2]), "+f"(c[3])
        : "r"(a[0]), "r"(a[1]), "r"(a[2]), "r"(a[3]), "r"(b[0]), "r"(b[1]));
}
__device__ __forceinline__ uint32_t pack_bf16x2(float lo_val, float hi_val) {
    __nv_bfloat16 l = __float2bfloat16(lo_val);
    __nv_bfloat16 h = __float2bfloat16(hi_val);
    return (uint32_t)__bfloat16_as_ushort(l) | ((uint32_t)__bfloat16_as_ushort(h) << 16);
}
__device__ __forceinline__ uint32_t smem_to_u32(const void* smem_ptr) {
    uint32_t addr;
    asm("{ .reg .u64 tmp; cvta.to.shared.u64 tmp, %1; cvt.u32.u64 %0, tmp; }"
        : "=r"(addr) : "l"(smem_ptr));
    return addr;
}
#define CP_ASYNC16(dst, src) \
    asm volatile("cp.async.cg.shared.global [%0], [%1], 16;" :: "r"(dst), "l"(src))
#define CP_COMMIT() asm volatile("cp.async.commit_group;" ::: "memory")
#define CP_WAIT(n)  asm volatile("cp.async.wait_group %0;" :: "n"(n) : "memory")

// ---------------------------------------------------------------------------
// Kernel 1 (consolidated front-end): split-tf32 MMA projections.
// which=0: Q=p@Wq -> g_Qth/g_Qtl [b][k][s] + q2 partials
// which=1: K=p@Wk -> g_Kth/g_Ktl [b][k][t] + k2 partials
// which=2: V=e@Wv -> g_Vph/g_Vpl bf16x2 [b][d][t/2]
// grid: (NR/128, Dd/64, 3)  block: 256 (4x2 warps of 32x32)
// ---------------------------------------------------------------------------
#define ASTR 137
#define BSTR 73
#define PROJ_SMEM ((2*32*ASTR + 2*32*BSTR)*4)   // 53760 B

__global__ __launch_bounds__(256, 2) void proj_mma_kernel(
    const float* __restrict__ p, const float* __restrict__ e,
    const float* __restrict__ Wq, const float* __restrict__ Wk,
    const float* __restrict__ Wv)
{
    const int which = blockIdx.z;
    const float* src = (which == 2) ? e : p;
    const float* W   = (which == 0) ? Wq : (which == 1) ? Wk : Wv;

    const int row0 = blockIdx.x * 128;           // global row over NR
    const int col0 = blockIdx.y * 64;
    const int b    = row0 >> 11;                 // Ss = 2048
    const int s_in = row0 & (Ss - 1);

    extern __shared__ float psm[];
    float* Ah = psm;
    float* Al = Ah + 32*ASTR;
    float* Bh = Al + 32*ASTR;
    float* Bl = Bh + 32*BSTR;
    const uint32_t* uAh = (const uint32_t*)Ah;
    const uint32_t* uAl = (const uint32_t*)Al;
    const uint32_t* uBh = (const uint32_t*)Bh;
    const uint32_t* uBl = (const uint32_t*)Bl;

    const int tid = threadIdx.x, lane = tid & 31, wid = tid >> 5;
    const int wm = wid & 3, wn = wid >> 2;
    const int r = lane >> 2, cc = lane & 3;

    float C[2][4][4] = {};

    for (int k0 = 0; k0 < Dd; k0 += 32) {
        __syncthreads();
        // stage A: src rows [row0,row0+128) x k [k0,k0+32) -> [k][m] hi/lo
        for (int l = tid; l < 1024; l += 256) {
            int m = l >> 3, c = l & 7;
            float4 v = *(const float4*)(src + (size_t)(row0 + m)*Dd + k0 + c*4);
            float f[4] = {v.x, v.y, v.z, v.w};
            #pragma unroll
            for (int j = 0; j < 4; j++) {
                int k = c*4 + j;
                float hf = __uint_as_float(f2tf32(f[j]));
                Ah[k*ASTR + m] = hf;
                Al[k*ASTR + m] = __uint_as_float(f2tf32(f[j] - hf));
            }
        }
        // stage B: W[k0+k][col0+n] -> [k][n] hi/lo
        for (int l = tid; l < 512; l += 256) {
            int k = l >> 4, c = l & 15;
            float4 v = *(const float4*)(W + (size_t)(k0 + k)*Dd + col0 + c*4);
            float f[4] = {v.x, v.y, v.z, v.w};
            #pragma unroll
            for (int j = 0; j < 4; j++) {
                int n = c*4 + j;
                float hf = __uint_as_float(f2tf32(f[j]));
                Bh[k*BSTR + n] = hf;
                Bl[k*BSTR + n] = __uint_as_float(f2tf32(f[j] - hf));
            }
        }
        __syncthreads();

        #pragma unroll
        for (int ks = 0; ks < 4; ks++) {
            const int kc = ks*8 + cc;
            uint32_t ah[2][4], al[2][4];
            #pragma unroll
            for (int mf = 0; mf < 2; mf++) {
                int mrow = wm*32 + mf*16 + r;
                ah[mf][0] = uAh[kc*ASTR + mrow];
                ah[mf][1] = uAh[kc*ASTR + mrow + 8];
                ah[mf][2] = uAh[(kc+4)*ASTR + mrow];
                ah[mf][3] = uAh[(kc+4)*ASTR + mrow + 8];
                al[mf][0] = uAl[kc*ASTR + mrow];
                al[mf][1] = uAl[kc*ASTR + mrow + 8];
                al[mf][2] = uAl[(kc+4)*ASTR + mrow];
                al[mf][3] = uAl[(kc+4)*ASTR + mrow + 8];
            }
            uint32_t bh[4][2], bl[4][2];
            #pragma unroll
            for (int nf = 0; nf < 4; nf++) {
                int ncol = wn*32 + nf*8 + r;
                bh[nf][0] = uBh[kc*BSTR + ncol];
                bh[nf][1] = uBh[(kc+4)*BSTR + ncol];
                bl[nf][0] = uBl[kc*BSTR + ncol];
                bl[nf][1] = uBl[(kc+4)*BSTR + ncol];
            }
            #pragma unroll
            for (int mf = 0; mf < 2; mf++)
                #pragma unroll
                for (int nf = 0; nf < 4; nf++) {
                    mma_tf32(C[mf][nf], ah[mf], bh[nf]);
                    mma_tf32(C[mf][nf], ah[mf], bl[nf]);
                    mma_tf32(C[mf][nf], al[mf], bh[nf]);
                }
        }
    }

    // ---- epilogue: bounce through smem (reuse Ah/Al region), write splits ----
    __syncthreads();
    float* Ts = psm;                 // 128 x 65 fp32 (8320 floats < 8768)
    #pragma unroll
    for (int mf = 0; mf < 2; mf++) {
        int s = wm*32 + mf*16 + r;
        #pragma unroll
        for (int nf = 0; nf < 4; nf++) {
            int n = wn*32 + nf*8 + 2*cc;
            Ts[s*65 + n]       = C[mf][nf][0];
            Ts[s*65 + n + 1]   = C[mf][nf][1];
            Ts[(s+8)*65 + n]     = C[mf][nf][2];
            Ts[(s+8)*65 + n + 1] = C[mf][nf][3];
        }
    }
    __syncthreads();

    if (which < 2) {
        float* dh = (which == 0) ? g_Qth : g_Kth;
        float* dl = (which == 0) ? g_Qtl : g_Ktl;
        float* nrm = (which == 0) ? g_q2 : g_k2;
        const int sc = tid & 127;
        const int kc0 = tid >> 7;
        float psum = 0.0f;
        #pragma unroll 8
        for (int i = 0; i < 32; i++) {
            int kc = kc0 + 2*i;
            float v = Ts[sc*65 + kc];
            psum += v * v;
            float hf = __uint_as_float(f2tf32(v));
            float lf = __uint_as_float(f2tf32(v - hf));
            size_t oi = ((size_t)(b*Dd + col0 + kc))*Ss + s_in + sc;
            dh[oi] = hf;
            dl[oi] = lf;
        }
        atomicAdd(&nrm[row0 + sc], psum);
    } else {
        for (int l = tid; l < 64*64; l += 256) {
            int kc = l >> 6, pr = l & 63;
            float v0 = Ts[(2*pr)*65 + kc];
            float v1 = Ts[(2*pr + 1)*65 + kc];
            __nv_bfloat16 h0 = __float2bfloat16(v0);
            __nv_bfloat16 h1 = __float2bfloat16(v1);
            size_t oi = ((size_t)(b*Dd + col0 + kc))*(Ss/2) + (s_in >> 1) + pr;
            g_Vph[oi] = (uint32_t)__bfloat16_as_ushort(h0)
                      | ((uint32_t)__bfloat16_as_ushort(h1) << 16);
            g_Vpl[oi] = pack_bf16x2(v0 - __bfloat162float(h0),
                                    v1 - __bfloat162float(h1));
        }
    }
}

// ---------------------------------------------------------------------------
// Kernel 2 (fused attn): per (b, leader-h, s-tile 128, chunk of 2 t-tiles):
//   Phase A: S = QK^T (split-tf32; Q frags direct from global, K slabs
//            cp.async double-buffered) -> P = exp(coef*d2) split-bf16 in smem
//   Phase B: per 64-wide d-chunk: OUT += P @ V^T, atomicAdd to leader head.
// grid: (16, 16, Bb*Hh)  block: 256
// ---------------------------------------------------------------------------
#define KSTR 72
#define PSTR 36
#define VSTR 36
#define U_OFF 18432          // uint32 offset of K/V region
#define FUSED_SMEM ((18432 + 9216)*4)   // 110592 B

__global__ __launch_bounds__(256, 2) void fused_attn_kernel(
    const float* __restrict__ gamma, float* __restrict__ out)
{
    const int si = blockIdx.x;
    const int chunk = blockIdx.y;
    if (chunk > si) return;
    const int z = blockIdx.z;
    const int b = z >> 3, h = z & 7;
    const float gh = gamma[h];
    for (int h2 = 0; h2 < h; h2++)
        if (gamma[h2] == gh) return;           // leader only
    const float coef = -1.0f / (-2.0f * gh + 1e-6f);

    const int s0 = si * 128;
    const int t0a = chunk * 128;
    const int t0b = t0a + 64;

    extern __shared__ uint32_t smu[];
    uint32_t* Ph[2] = { smu,        smu + 9216 };
    uint32_t* Pl[2] = { smu + 4608, smu + 13824 };
    uint32_t* U = smu + U_OFF;                  // K double-buffer / V tiles
    const uint32_t kbyte = smem_to_u32((const void*)U);

    const int tid = threadIdx.x, lane = tid & 31, wid = tid >> 5;
    const int wm = wid & 3, wn = wid >> 2;
    const int r = lane >> 2, cc = lane & 3;

    const float* Qgh = g_Qth + (size_t)b*Dd*Ss;
    const float* Qgl = g_Qtl + (size_t)b*Dd*Ss;
    const float* Kgh = g_Kth + (size_t)b*Dd*Ss;
    const float* Kgl = g_Ktl + (size_t)b*Dd*Ss;
    const uint32_t* Qgh32 = (const uint32_t*)Qgh;
    const uint32_t* Qgl32 = (const uint32_t*)Qgl;

    // ---------------- Phase A ----------------
    float C0[2][4][4] = {}, C1[2][4][4] = {};

    const int ck = tid >> 4, ccp = tid & 15;    // cp.async role: k-row, 16B chunk
    #define ISSUE_SLAB(sl, buf) do { \
        size_t go = (size_t)((sl)*16 + ck)*Ss + ccp*4; \
        uint32_t d0 = kbyte + (uint32_t)((buf)*4608 + ck*KSTR + ccp*4) * 4u; \
        CP_ASYNC16(d0,            (const void*)(Kgh + go + t0a)); \
        CP_ASYNC16(d0 + 1152*4,   (const void*)(Kgl + go + t0a)); \
        CP_ASYNC16(d0 + 2304*4,   (const void*)(Kgh + go + t0b)); \
        CP_ASYNC16(d0 + 3456*4,   (const void*)(Kgl + go + t0b)); \
    } while (0)

    ISSUE_SLAB(0, 0); CP_COMMIT();

    for (int sl = 0; sl < 16; sl++) {
        if (sl + 1 < 16) { ISSUE_SLAB(sl + 1, (sl + 1) & 1); CP_COMMIT(); CP_WAIT(1); }
        else             { CP_WAIT(0); }
        __syncthreads();

        const int k0 = sl * 16;
        const uint32_t* uKh0 = U + (sl & 1)*4608;
        const uint32_t* uKl0 = uKh0 + 1152;
        const uint32_t* uKh1 = uKh0 + 2304;
        const uint32_t* uKl1 = uKh0 + 3456;

        #pragma unroll
        for (int ks = 0; ks < 2; ks++) {
            const int kc = ks*8 + cc;
            const size_t qb = (size_t)(k0 + kc)*Ss + s0;
            uint32_t ah[2][4], al[2][4];
            #pragma unroll
            for (int mf = 0; mf < 2; mf++) {
                int mrow = wm*32 + mf*16 + r;
                ah[mf][0] = Qgh32[qb + mrow];
                ah[mf][1] = Qgh32[qb + mrow + 8];
                ah[mf][2] = Qgh32[qb + 4*Ss + mrow];
                ah[mf][3] = Qgh32[qb + 4*Ss + mrow + 8];
                al[mf][0] = Qgl32[qb + mrow];
                al[mf][1] = Qgl32[qb + mrow + 8];
                al[mf][2] = Qgl32[qb + 4*Ss + mrow];
                al[mf][3] = Qgl32[qb + 4*Ss + mrow + 8];
            }
            {   // tile 0
                uint32_t bh[4][2], bl[4][2];
                #pragma unroll
                for (int nf = 0; nf < 4; nf++) {
                    int ncol = wn*32 + nf*8 + r;
                    bh[nf][0] = uKh0[kc*KSTR + ncol];
                    bh[nf][1] = uKh0[(kc+4)*KSTR + ncol];
                    bl[nf][0] = uKl0[kc*KSTR + ncol];
                    bl[nf][1] = uKl0[(kc+4)*KSTR + ncol];
                }
                #pragma unroll
                for (int mf = 0; mf < 2; mf++)
                    #pragma unroll
                    for (int nf = 0; nf < 4; nf++) {
                        mma_tf32(C0[mf][nf], ah[mf], bh[nf]);
                        mma_tf32(C0[mf][nf], ah[mf], bl[nf]);
                        mma_tf32(C0[mf][nf], al[mf], bh[nf]);
                    }
            }
            {   // tile 1
                uint32_t bh[4][2], bl[4][2];
                #pragma unroll
                for (int nf = 0; nf < 4; nf++) {
                    int ncol = wn*32 + nf*8 + r;
                    bh[nf][0] = uKh1[kc*KSTR + ncol];
                    bh[nf][1] = uKh1[(kc+4)*KSTR + ncol];
                    bl[nf][0] = uKl1[kc*KSTR + ncol];
                    bl[nf][1] = uKl1[(kc+4)*KSTR + ncol];
                }
                #pragma unroll
                for (int mf = 0; mf < 2; mf++)
                    #pragma unroll
                    for (int nf = 0; nf < 4; nf++) {
                        mma_tf32(C1[mf][nf], ah[mf], bh[nf]);
                        mma_tf32(C1[mf][nf], ah[mf], bl[nf]);
                        mma_tf32(C1[mf][nf], al[mf], bh[nf]);
                    }
            }
        }
        __syncthreads();
    }

    // ---------------- Epilogue A: P = exp(coef * d2), split bf16 --------
    #pragma unroll
    for (int tl = 0; tl < 2; tl++) {
        const int t0 = tl ? t0b : t0a;
        float (*C)[4][4] = tl ? C1 : C0;
        #pragma unroll
        for (int mf = 0; mf < 2; mf++) {
            int sl2 = wm*32 + mf*16 + r;
            int sg = s0 + sl2;
            float q2a = g_q2[b*Ss + sg];
            float q2c = g_q2[b*Ss + sg + 8];
            #pragma unroll
            for (int nf = 0; nf < 4; nf++) {
                int tg = t0 + wn*32 + nf*8 + 2*cc;
                float k2a = g_k2[b*Ss + tg];
                float k2b = g_k2[b*Ss + tg + 1];
                float p00 = (tg     > sg) ? 0.0f : __expf(coef * fmaxf(q2a + k2a - 2.0f*C[mf][nf][0], 0.0f));
                float p01 = (tg + 1 > sg) ? 0.0f : __expf(coef * fmaxf(q2a + k2b - 2.0f*C[mf][nf][1], 0.0f));
                float p10 = (tg     > sg + 8) ? 0.0f : __expf(coef * fmaxf(q2c + k2a - 2.0f*C[mf][nf][2], 0.0f));
                float p11 = (tg + 1 > sg + 8) ? 0.0f : __expf(coef * fmaxf(q2c + k2b - 2.0f*C[mf][nf][3], 0.0f));
                int pidx = wn*16 + nf*4 + cc;
                __nv_bfloat16 h00 = __float2bfloat16(p00);
                __nv_bfloat16 h01 = __float2bfloat16(p01);
                __nv_bfloat16 h10 = __float2bfloat16(p10);
                __nv_bfloat16 h11 = __float2bfloat16(p11);
                Ph[tl][sl2*PSTR + pidx] = (uint32_t)__bfloat16_as_ushort(h00)
                                        | ((uint32_t)__bfloat16_as_ushort(h01) << 16);
                Ph[tl][(sl2+8)*PSTR + pidx] = (uint32_t)__bfloat16_as_ushort(h10)
                                            | ((uint32_t)__bfloat16_as_ushort(h11) << 16);
                Pl[tl][sl2*PSTR + pidx] = pack_bf16x2(p00 - __bfloat162float(h00),
                                                      p01 - __bfloat162float(h01));
                Pl[tl][(sl2+8)*PSTR + pidx] = pack_bf16x2(p10 - __bfloat162float(h10),
                                                          p11 - __bfloat162float(h11));
            }
        }
    }
    __syncthreads();

    // ---------------- Phase B: OUT += P @ V^T per d-chunk ----------------
    uint32_t* Vh[2] = { U,        U + 4608 };
    uint32_t* Vl[2] = { U + 2304, U + 6912 };
    float* o = out + ((size_t)(b*Hh + h)*Ss)*Dd;

    for (int dch = 0; dch < 4; dch++) {
        for (int l = tid; l < 512; l += 256) {
            int d = l >> 3, c = l & 7;
            size_t gia = ((size_t)(b*Dd + dch*64 + d))*(Ss/2) + t0a/2 + c*4;
            size_t gib = ((size_t)(b*Dd + dch*64 + d))*(Ss/2) + t0b/2 + c*4;
            *(uint4*)&Vh[0][d*VSTR + c*4] = *(const uint4*)(g_Vph + gia);
            *(uint4*)&Vl[0][d*VSTR + c*4] = *(const uint4*)(g_Vpl + gia);
            *(uint4*)&Vh[1][d*VSTR + c*4] = *(const uint4*)(g_Vph + gib);
            *(uint4*)&Vl[1][d*VSTR + c*4] = *(const uint4*)(g_Vpl + gib);
        }
        __syncthreads();

        float C[2][4][4] = {};
        #pragma unroll
        for (int tl = 0; tl < 2; tl++) {
            #pragma unroll
            for (int ks = 0; ks < 4; ks++) {
                const int pc = ks*8 + cc;
                uint32_t ah[2][4], al[2][4];
                #pragma unroll
                for (int mf = 0; mf < 2; mf++) {
                    int srow = wm*32 + mf*16 + r;
                    ah[mf][0] = Ph[tl][srow*PSTR + pc];
                    ah[mf][1] = Ph[tl][(srow+8)*PSTR + pc];
                    ah[mf][2] = Ph[tl][srow*PSTR + pc + 4];
                    ah[mf][3] = Ph[tl][(srow+8)*PSTR + pc + 4];
                    al[mf][0] = Pl[tl][srow*PSTR + pc];
                    al[mf][1] = Pl[tl][(srow+8)*PSTR + pc];
                    al[mf][2] = Pl[tl][srow*PSTR + pc + 4];
                    al[mf][3] = Pl[tl][(srow+8)*PSTR + pc + 4];
                }
                uint32_t bh[4][2], bl[4][2];
                #pragma unroll
                for (int nf = 0; nf < 4; nf++) {
                    int dcol = wn*32 + nf*8 + r;
                    bh[nf][0] = Vh[tl][dcol*VSTR + pc];
                    bh[nf][1] = Vh[tl][dcol*VSTR + pc + 4];
                    bl[nf][0] = Vl[tl][dcol*VSTR + pc];
                    bl[nf][1] = Vl[tl][dcol*VSTR + pc + 4];
                }
                #pragma unroll
                for (int mf = 0; mf < 2; mf++)
                    #pragma unroll
                    for (int nf = 0; nf < 4; nf++) {
                        mma_bf16(C[mf][nf], ah[mf], bh[nf]);
                        mma_bf16(C[mf][nf], ah[mf], bl[nf]);
                        mma_bf16(C[mf][nf], al[mf], bh[nf]);
                    }
            }
        }
        #pragma unroll
        for (int mf = 0; mf < 2; mf++) {
            int s = s0 + wm*32 + mf*16 + r;
            #pragma unroll
            for (int nf = 0; nf < 4; nf++) {
                int d = dch*64 + wn*32 + nf*8 + 2*cc;
                atomicAdd(&o[(size_t)s*Dd + d],         C[mf][nf][0]);
                atomicAdd(&o[(size_t)s*Dd + d + 1],     C[mf][nf][1]);
                atomicAdd(&o[(size_t)(s+8)*Dd + d],     C[mf][nf][2]);
                atomicAdd(&o[(size_t)(s+8)*Dd + d + 1], C[mf][nf][3]);
            }
        }
        __syncthreads();
    }
}

// ---------------------------------------------------------------------------
// Kernel 3: broadcast leader head output to duplicate-gamma heads.
// ---------------------------------------------------------------------------
__global__ __launch_bounds__(256) void bcast_kernel(
    const float* __restrict__ gamma, float* __restrict__ out)
{
    const int h = blockIdx.y, b = blockIdx.z;
    const float gh = gamma[h];
    int leader = h;
    for (int h2 = 0; h2 < h; h2++)
        if (gamma[h2] == gh) { leader = h2; break; }
    if (leader == h) return;

    size_t idx = ((size_t)blockIdx.x * 256 + threadIdx.x) * 4;
    const float4 v = *(const float4*)&out[((size_t)(b*Hh + leader)*Ss)*Dd + idx];
    *(float4*)&out[((size_t)(b*Hh + h)*Ss)*Dd + idx] = v;
}

// ---------------------------------------------------------------------------
extern "C" void kernel_launch(void* const* d_in, const int* in_sizes, int n_in,
                              void* d_out, int out_size)
{
    // metadata order: x, e, p, W_q, W_k, W_v, gamma
    const float* e     = (const float*)d_in[1];
    const float* p     = (const float*)d_in[2];
    const float* Wq    = (const float*)d_in[3];
    const float* Wk    = (const float*)d_in[4];
    const float* Wv    = (const float*)d_in[5];
    const float* gamma = (const float*)d_in[6];
    float* out = (float*)d_out;

    static bool init_done = false;
    static void *q2p = nullptr, *k2p = nullptr;
    if (!init_done) {
        cudaFuncSetAttribute(proj_mma_kernel,
                             cudaFuncAttributeMaxDynamicSharedMemorySize, PROJ_SMEM);
        cudaFuncSetAttribute(fused_attn_kernel,
                             cudaFuncAttributeMaxDynamicSharedMemorySize, FUSED_SMEM);
        cudaGetSymbolAddress(&q2p, g_q2);
        cudaGetSymbolAddress(&k2p, g_k2);
        init_done = true;
    }

    // zero norm accumulators (proj epilogue atomicAdds into them)
    cudaMemsetAsync(q2p, 0, NR * sizeof(float));
    cudaMemsetAsync(k2p, 0, NR * sizeof(float));

    dim3 gproj(NR/128, Dd/64, 3);
    proj_mma_kernel<<<gproj, 256, PROJ_SMEM>>>(p, e, Wq, Wk, Wv);

    cudaMemsetAsync(d_out, 0, (size_t)out_size * sizeof(float));

    dim3 gf(16, 16, Bb*Hh);
    fused_attn_kernel<<<gf, 256, FUSED_SMEM>>>(gamma, out);

    dim3 gb((Ss*Dd)/1024, Hh, Bb);
    bcast_kernel<<<gb, 256>>>(gamma, out);
}

// round 10
// speedup vs baseline: 1.5761x; 1.2011x over previous
#include <cuda_runtime.h>
#include <cuda_bf16.h>
#include <cstdint>

// Problem constants
#define Bb 2
#define Ss 2048
#define Dd 256
#define Hh 8
#define NR (Bb*Ss)

// Scratch: raw transposed operands + packed V + norms
__device__ __align__(16) float g_Qt[Bb*Dd*Ss];     // raw fp32, [b][k][s]
__device__ __align__(16) float g_Kt[Bb*Dd*Ss];     // raw fp32, [b][k][t]
__device__ __align__(16) uint32_t g_Vph[Bb*Dd*(Ss/2)], g_Vpl[Bb*Dd*(Ss/2)]; // bf16x2 pairs
__device__ float g_q2[NR];
__device__ float g_k2[NR];

// ===================== helpers =====================
__device__ __forceinline__ uint32_t f2tf32(float f) {
    uint32_t r;
    asm("cvt.rna.tf32.f32 %0, %1;" : "=r"(r) : "f"(f));
    return r;
}
__device__ __forceinline__ void split_tf32(float v, uint32_t& hi, uint32_t& lo) {
    hi = f2tf32(v);
    lo = f2tf32(v - __uint_as_float(hi));
}
__device__ __forceinline__ void mma_tf32(float* c, const uint32_t* a, const uint32_t* b) {
    asm volatile(
        "mma.sync.aligned.m16n8k8.row.col.f32.tf32.tf32.f32 "
        "{%0,%1,%2,%3}, {%4,%5,%6,%7}, {%8,%9}, {%0,%1,%2,%3};"
        : "+f"(c[0]), "+f"(c[1]), "+f"(c[2]), "+f"(c[3])
        : "r"(a[0]), "r"(a[1]), "r"(a[2]), "r"(a[3]), "r"(b[0]), "r"(b[1]));
}
__device__ __forceinline__ void mma_bf16(float* c, const uint32_t* a, const uint32_t* b) {
    asm volatile(
        "mma.sync.aligned.m16n8k16.row.col.f32.bf16.bf16.f32 "
        "{%0,%1,%2,%3}, {%4,%5,%6,%7}, {%8,%9}, {%0,%1,%2,%3};"
        : "+f"(c[0]), "+f"(c[1]), "+f"(c[2]), "+f"(c[3])
        : "r"(a[0]), "r"(a[1]), "r"(a[2]), "r"(a[3]), "r"(b[0]), "r"(b[1]));
}
__device__ __forceinline__ uint32_t pack_bf16x2(float lo_val, float hi_val) {
    __nv_bfloat16 l = __float2bfloat16(lo_val);
    __nv_bfloat16 h = __float2bfloat16(hi_val);
    return (uint32_t)__bfloat16_as_ushort(l) | ((uint32_t)__bfloat16_as_ushort(h) << 16);
}
__device__ __forceinline__ uint32_t smem_to_u32(const void* smem_ptr) {
    uint32_t addr;
    asm("{ .reg .u64 tmp; cvta.to.shared.u64 tmp, %1; cvt.u32.u64 %0, tmp; }"
        : "=r"(addr) : "l"(smem_ptr));
    return addr;
}
#define CP_ASYNC16(dst, src) \
    asm volatile("cp.async.cg.shared.global [%0], [%1], 16;" :: "r"(dst), "l"(src))
#define CP_COMMIT() asm volatile("cp.async.commit_group;" ::: "memory")
#define CP_WAIT(n)  asm volatile("cp.async.wait_group %0;" :: "n"(n) : "memory")

// ---------------------------------------------------------------------------
// Kernel 1: split-tf32 MMA projections, cp.async raw staging + register split.
// which=0: Q=p@Wq -> g_Qt raw [b][k][s] + q2   which=1: K -> g_Kt + k2
// which=2: V=e@Wv -> g_Vph/g_Vpl bf16x2 [b][d][t/2]
// grid: (NR/128, Dd/64, 3)  block: 256 (4x2 warps of 32x32)
// ---------------------------------------------------------------------------
#define MSTR 36     // A raw [m][k] stride (floats): bank = 4r+cc, 16B-aligned rows
#define BSTR 72     // B raw [k][n] stride: bank = 8cc+r
// smem floats: A 2x4608, B 2x2304 -> 13824 floats
#define PROJ_SMEM (13824*4)   // 55296 B

__global__ __launch_bounds__(256, 2) void proj_mma_kernel(
    const float* __restrict__ p, const float* __restrict__ e,
    const float* __restrict__ Wq, const float* __restrict__ Wk,
    const float* __restrict__ Wv)
{
    const int which = blockIdx.z;
    const float* src = (which == 2) ? e : p;
    const float* W   = (which == 0) ? Wq : (which == 1) ? Wk : Wv;

    const int row0 = blockIdx.x * 128;
    const int col0 = blockIdx.y * 64;
    const int b    = row0 >> 11;
    const int s_in = row0 & (Ss - 1);

    extern __shared__ float psm[];
    const uint32_t smb = smem_to_u32(psm);
    // A buffers at 0 / 4608 floats; B buffers at 9216 / 11520 floats

    const int tid = threadIdx.x, lane = tid & 31, wid = tid >> 5;
    const int wm = wid & 3, wn = wid >> 2;
    const int r = lane >> 2, cc = lane & 3;

    float C[2][4][4] = {};

    #define P_ISSUE(sl, buf) do { \
        const int k0i = (sl)*32; \
        for (int i = tid; i < 1024; i += 256) { \
            int row = i >> 3, ch = i & 7; \
            CP_ASYNC16(smb + (uint32_t)(((buf)*4608 + row*MSTR + ch*4))*4u, \
                       (const void*)(src + (size_t)(row0 + row)*Dd + k0i + ch*4)); \
        } \
        for (int i = tid; i < 512; i += 256) { \
            int row = i >> 4, ch = i & 15; \
            CP_ASYNC16(smb + (uint32_t)((9216 + (buf)*2304 + row*BSTR + ch*4))*4u, \
                       (const void*)(W + (size_t)(k0i + row)*Dd + col0 + ch*4)); \
        } \
    } while (0)

    P_ISSUE(0, 0); CP_COMMIT();

    for (int sl = 0; sl < 8; sl++) {
        if (sl + 1 < 8) { P_ISSUE(sl + 1, (sl + 1) & 1); CP_COMMIT(); CP_WAIT(1); }
        else            { CP_WAIT(0); }
        __syncthreads();

        const float* Ab = psm + (sl & 1)*4608;
        const float* Bbuf = psm + 9216 + (sl & 1)*2304;

        #pragma unroll
        for (int ks = 0; ks < 4; ks++) {
            const int kc = ks*8 + cc;
            uint32_t ah[2][4], al[2][4];
            #pragma unroll
            for (int mf = 0; mf < 2; mf++) {
                int m0 = wm*32 + mf*16 + r;
                float a0 = Ab[m0*MSTR + kc];
                float a1 = Ab[(m0+8)*MSTR + kc];
                float a2 = Ab[m0*MSTR + kc + 4];
                float a3 = Ab[(m0+8)*MSTR + kc + 4];
                split_tf32(a0, ah[mf][0], al[mf][0]);
                split_tf32(a1, ah[mf][1], al[mf][1]);
                split_tf32(a2, ah[mf][2], al[mf][2]);
                split_tf32(a3, ah[mf][3], al[mf][3]);
            }
            uint32_t bh[4][2], bl[4][2];
            #pragma unroll
            for (int nf = 0; nf < 4; nf++) {
                int ncol = wn*32 + nf*8 + r;
                float b0 = Bbuf[kc*BSTR + ncol];
                float b1 = Bbuf[(kc+4)*BSTR + ncol];
                split_tf32(b0, bh[nf][0], bl[nf][0]);
                split_tf32(b1, bh[nf][1], bl[nf][1]);
            }
            #pragma unroll
            for (int mf = 0; mf < 2; mf++)
                #pragma unroll
                for (int nf = 0; nf < 4; nf++) {
                    mma_tf32(C[mf][nf], ah[mf], bh[nf]);
                    mma_tf32(C[mf][nf], ah[mf], bl[nf]);
                    mma_tf32(C[mf][nf], al[mf], bh[nf]);
                }
        }
        __syncthreads();
    }

    // ---- epilogue: bounce through smem, write raw transposed + norms ----
    float* Ts = psm;                 // 128 x 65 fp32
    #pragma unroll
    for (int mf = 0; mf < 2; mf++) {
        int s = wm*32 + mf*16 + r;
        #pragma unroll
        for (int nf = 0; nf < 4; nf++) {
            int n = wn*32 + nf*8 + 2*cc;
            Ts[s*65 + n]         = C[mf][nf][0];
            Ts[s*65 + n + 1]     = C[mf][nf][1];
            Ts[(s+8)*65 + n]     = C[mf][nf][2];
            Ts[(s+8)*65 + n + 1] = C[mf][nf][3];
        }
    }
    __syncthreads();

    if (which < 2) {
        float* dst = (which == 0) ? g_Qt : g_Kt;
        float* nrm = (which == 0) ? g_q2 : g_k2;
        const int sc = tid & 127;
        const int kc0 = tid >> 7;
        float psum = 0.0f;
        #pragma unroll 8
        for (int i = 0; i < 32; i++) {
            int kc = kc0 + 2*i;
            float v = Ts[sc*65 + kc];
            psum += v * v;
            dst[((size_t)(b*Dd + col0 + kc))*Ss + s_in + sc] = v;
        }
        atomicAdd(&nrm[row0 + sc], psum);
    } else {
        for (int l = tid; l < 64*64; l += 256) {
            int kc = l >> 6, pr = l & 63;
            float v0 = Ts[(2*pr)*65 + kc];
            float v1 = Ts[(2*pr + 1)*65 + kc];
            __nv_bfloat16 h0 = __float2bfloat16(v0);
            __nv_bfloat16 h1 = __float2bfloat16(v1);
            size_t oi = ((size_t)(b*Dd + col0 + kc))*(Ss/2) + (s_in >> 1) + pr;
            g_Vph[oi] = (uint32_t)__bfloat16_as_ushort(h0)
                      | ((uint32_t)__bfloat16_as_ushort(h1) << 16);
            g_Vpl[oi] = pack_bf16x2(v0 - __bfloat162float(h0),
                                    v1 - __bfloat162float(h1));
        }
    }
}

// ---------------------------------------------------------------------------
// Kernel 2 (fused attn): Phase A: S = QK^T — Q and K slabs cp.async RAW,
// double-buffered, register tf32 split -> P = exp(coef*d2) split-bf16 in smem.
// Phase B: per 64-wide d-chunk, OUT += P @ V^T, atomicAdd to leader head.
// grid: (16, 16, Bb*Hh)  block: 256
// ---------------------------------------------------------------------------
#define QSTR 136    // Q raw [k][s] stride: bank = 8cc+r
#define KSTR 72     // K raw [k][t] stride
#define PSTR 36
#define VSTR 36
#define U_OFF 18432
// U region (uint32): Qbuf0=0(2176) Qbuf1=2176 Kbuf0=4352(2304) Kbuf1=6656 -> 8960 <= 9216
#define FUSED_SMEM ((18432 + 9216)*4)   // 110592 B

__global__ __launch_bounds__(256, 2) void fused_attn_kernel(
    const float* __restrict__ gamma, float* __restrict__ out)
{
    const int si = blockIdx.x;
    const int chunk = blockIdx.y;
    if (chunk > si) return;
    const int z = blockIdx.z;
    const int b = z >> 3, h = z & 7;
    const float gh = gamma[h];
    for (int h2 = 0; h2 < h; h2++)
        if (gamma[h2] == gh) return;           // leader only
    const float coef = -1.0f / (-2.0f * gh + 1e-6f);

    const int s0 = si * 128;
    const int t0a = chunk * 128;
    const int t0b = t0a + 64;

    extern __shared__ uint32_t smu[];
    uint32_t* Ph[2] = { smu,        smu + 9216 };
    uint32_t* Pl[2] = { smu + 4608, smu + 13824 };
    uint32_t* U = smu + U_OFF;
    const uint32_t ub = smem_to_u32((const void*)U);

    const int tid = threadIdx.x, lane = tid & 31, wid = tid >> 5;
    const int wm = wid & 3, wn = wid >> 2;
    const int r = lane >> 2, cc = lane & 3;

    const float* Qg = g_Qt + (size_t)b*Dd*Ss;
    const float* Kg = g_Kt + (size_t)b*Dd*Ss;

    // ---------------- Phase A ----------------
    float C0[2][4][4] = {}, C1[2][4][4] = {};

    #define QK_ISSUE(sl, buf) do { \
        const int k0i = (sl)*16; \
        for (int i = tid; i < 512; i += 256) { \
            int row = i >> 5, ch = i & 31; \
            CP_ASYNC16(ub + (uint32_t)((buf)*2176 + row*QSTR + ch*4)*4u, \
                       (const void*)(Qg + (size_t)(k0i + row)*Ss + s0 + ch*4)); \
        } \
        { int row = tid >> 4, ch = tid & 15; \
          CP_ASYNC16(ub + (uint32_t)(4352 + (buf)*2304 + row*KSTR + ch*4)*4u, \
                     (const void*)(Kg + (size_t)(k0i + row)*Ss + t0a + ch*4)); \
          CP_ASYNC16(ub + (uint32_t)(4352 + (buf)*2304 + 1152 + row*KSTR + ch*4)*4u, \
                     (const void*)(Kg + (size_t)(k0i + row)*Ss + t0b + ch*4)); } \
    } while (0)

    QK_ISSUE(0, 0); CP_COMMIT();

    for (int sl = 0; sl < 16; sl++) {
        if (sl + 1 < 16) { QK_ISSUE(sl + 1, (sl + 1) & 1); CP_COMMIT(); CP_WAIT(1); }
        else             { CP_WAIT(0); }
        __syncthreads();

        const float* Qb = (const float*)(U + (sl & 1)*2176);
        const float* Kb0 = (const float*)(U + 4352 + (sl & 1)*2304);
        const float* Kb1 = Kb0 + 1152;

        #pragma unroll
        for (int ks = 0; ks < 2; ks++) {
            const int kc = ks*8 + cc;
            uint32_t ah[2][4], al[2][4];
            #pragma unroll
            for (int mf = 0; mf < 2; mf++) {
                int m0 = wm*32 + mf*16 + r;
                float a0 = Qb[kc*QSTR + m0];
                float a1 = Qb[kc*QSTR + m0 + 8];
                float a2 = Qb[(kc+4)*QSTR + m0];
                float a3 = Qb[(kc+4)*QSTR + m0 + 8];
                split_tf32(a0, ah[mf][0], al[mf][0]);
                split_tf32(a1, ah[mf][1], al[mf][1]);
                split_tf32(a2, ah[mf][2], al[mf][2]);
                split_tf32(a3, ah[mf][3], al[mf][3]);
            }
            {   // tile 0
                uint32_t bh[4][2], bl[4][2];
                #pragma unroll
                for (int nf = 0; nf < 4; nf++) {
                    int ncol = wn*32 + nf*8 + r;
                    split_tf32(Kb0[kc*KSTR + ncol],     bh[nf][0], bl[nf][0]);
                    split_tf32(Kb0[(kc+4)*KSTR + ncol], bh[nf][1], bl[nf][1]);
                }
                #pragma unroll
                for (int mf = 0; mf < 2; mf++)
                    #pragma unroll
                    for (int nf = 0; nf < 4; nf++) {
                        mma_tf32(C0[mf][nf], ah[mf], bh[nf]);
                        mma_tf32(C0[mf][nf], ah[mf], bl[nf]);
                        mma_tf32(C0[mf][nf], al[mf], bh[nf]);
                    }
            }
            {   // tile 1
                uint32_t bh[4][2], bl[4][2];
                #pragma unroll
                for (int nf = 0; nf < 4; nf++) {
                    int ncol = wn*32 + nf*8 + r;
                    split_tf32(Kb1[kc*KSTR + ncol],     bh[nf][0], bl[nf][0]);
                    split_tf32(Kb1[(kc+4)*KSTR + ncol], bh[nf][1], bl[nf][1]);
                }
                #pragma unroll
                for (int mf = 0; mf < 2; mf++)
                    #pragma unroll
                    for (int nf = 0; nf < 4; nf++) {
                        mma_tf32(C1[mf][nf], ah[mf], bh[nf]);
                        mma_tf32(C1[mf][nf], ah[mf], bl[nf]);
                        mma_tf32(C1[mf][nf], al[mf], bh[nf]);
                    }
            }
        }
        __syncthreads();
    }

    // ---------------- Epilogue A: P = exp(coef * d2), split bf16 --------
    #pragma unroll
    for (int tl = 0; tl < 2; tl++) {
        const int t0 = tl ? t0b : t0a;
        float (*C)[4][4] = tl ? C1 : C0;
        #pragma unroll
        for (int mf = 0; mf < 2; mf++) {
            int sl2 = wm*32 + mf*16 + r;
            int sg = s0 + sl2;
            float q2a = g_q2[b*Ss + sg];
            float q2c = g_q2[b*Ss + sg + 8];
            #pragma unroll
            for (int nf = 0; nf < 4; nf++) {
                int tg = t0 + wn*32 + nf*8 + 2*cc;
                float k2a = g_k2[b*Ss + tg];
                float k2b = g_k2[b*Ss + tg + 1];
                float p00 = (tg     > sg) ? 0.0f : __expf(coef * fmaxf(q2a + k2a - 2.0f*C[mf][nf][0], 0.0f));
                float p01 = (tg + 1 > sg) ? 0.0f : __expf(coef * fmaxf(q2a + k2b - 2.0f*C[mf][nf][1], 0.0f));
                float p10 = (tg     > sg + 8) ? 0.0f : __expf(coef * fmaxf(q2c + k2a - 2.0f*C[mf][nf][2], 0.0f));
                float p11 = (tg + 1 > sg + 8) ? 0.0f : __expf(coef * fmaxf(q2c + k2b - 2.0f*C[mf][nf][3], 0.0f));
                int pidx = wn*16 + nf*4 + cc;
                __nv_bfloat16 h00 = __float2bfloat16(p00);
                __nv_bfloat16 h01 = __float2bfloat16(p01);
                __nv_bfloat16 h10 = __float2bfloat16(p10);
                __nv_bfloat16 h11 = __float2bfloat16(p11);
                Ph[tl][sl2*PSTR + pidx] = (uint32_t)__bfloat16_as_ushort(h00)
                                        | ((uint32_t)__bfloat16_as_ushort(h01) << 16);
                Ph[tl][(sl2+8)*PSTR + pidx] = (uint32_t)__bfloat16_as_ushort(h10)
                                            | ((uint32_t)__bfloat16_as_ushort(h11) << 16);
                Pl[tl][sl2*PSTR + pidx] = pack_bf16x2(p00 - __bfloat162float(h00),
                                                      p01 - __bfloat162float(h01));
                Pl[tl][(sl2+8)*PSTR + pidx] = pack_bf16x2(p10 - __bfloat162float(h10),
                                                          p11 - __bfloat162float(h11));
            }
        }
    }
    __syncthreads();

    // ---------------- Phase B: OUT += P @ V^T per d-chunk ----------------
    uint32_t* Vh[2] = { U,        U + 4608 };
    uint32_t* Vl[2] = { U + 2304, U + 6912 };
    float* o = out + ((size_t)(b*Hh + h)*Ss)*Dd;

    for (int dch = 0; dch < 4; dch++) {
        for (int l = tid; l < 512; l += 256) {
            int d = l >> 3, c = l & 7;
            size_t gia = ((size_t)(b*Dd + dch*64 + d))*(Ss/2) + t0a/2 + c*4;
            size_t gib = ((size_t)(b*Dd + dch*64 + d))*(Ss/2) + t0b/2 + c*4;
            *(uint4*)&Vh[0][d*VSTR + c*4] = *(const uint4*)(g_Vph + gia);
            *(uint4*)&Vl[0][d*VSTR + c*4] = *(const uint4*)(g_Vpl + gia);
            *(uint4*)&Vh[1][d*VSTR + c*4] = *(const uint4*)(g_Vph + gib);
            *(uint4*)&Vl[1][d*VSTR + c*4] = *(const uint4*)(g_Vpl + gib);
        }
        __syncthreads();

        float C[2][4][4] = {};
        #pragma unroll
        for (int tl = 0; tl < 2; tl++) {
            #pragma unroll
            for (int ks = 0; ks < 4; ks++) {
                const int pc = ks*8 + cc;
                uint32_t ah[2][4], al[2][4];
                #pragma unroll
                for (int mf = 0; mf < 2; mf++) {
                    int srow = wm*32 + mf*16 + r;
                    ah[mf][0] = Ph[tl][srow*PSTR + pc];
                    ah[mf][1] = Ph[tl][(srow+8)*PSTR + pc];
                    ah[mf][2] = Ph[tl][srow*PSTR + pc + 4];
                    ah[mf][3] = Ph[tl][(srow+8)*PSTR + pc + 4];
                    al[mf][0] = Pl[tl][srow*PSTR + pc];
                    al[mf][1] = Pl[tl][(srow+8)*PSTR + pc];
                    al[mf][2] = Pl[tl][srow*PSTR + pc + 4];
                    al[mf][3] = Pl[tl][(srow+8)*PSTR + pc + 4];
                }
                uint32_t bh[4][2], bl[4][2];
                #pragma unroll
                for (int nf = 0; nf < 4; nf++) {
                    int dcol = wn*32 + nf*8 + r;
                    bh[nf][0] = Vh[tl][dcol*VSTR + pc];
                    bh[nf][1] = Vh[tl][dcol*VSTR + pc + 4];
                    bl[nf][0] = Vl[tl][dcol*VSTR + pc];
                    bl[nf][1] = Vl[tl][dcol*VSTR + pc + 4];
                }
                #pragma unroll
                for (int mf = 0; mf < 2; mf++)
                    #pragma unroll
                    for (int nf = 0; nf < 4; nf++) {
                        mma_bf16(C[mf][nf], ah[mf], bh[nf]);
                        mma_bf16(C[mf][nf], ah[mf], bl[nf]);
                        mma_bf16(C[mf][nf], al[mf], bh[nf]);
                    }
            }
        }
        #pragma unroll
        for (int mf = 0; mf < 2; mf++) {
            int s = s0 + wm*32 + mf*16 + r;
            #pragma unroll
            for (int nf = 0; nf < 4; nf++) {
                int d = dch*64 + wn*32 + nf*8 + 2*cc;
                atomicAdd(&o[(size_t)s*Dd + d],         C[mf][nf][0]);
                atomicAdd(&o[(size_t)s*Dd + d + 1],     C[mf][nf][1]);
                atomicAdd(&o[(size_t)(s+8)*Dd + d],     C[mf][nf][2]);
                atomicAdd(&o[(size_t)(s+8)*Dd + d + 1], C[mf][nf][3]);
            }
        }
        __syncthreads();
    }
}

// ---------------------------------------------------------------------------
// Kernel 3: broadcast leader head output to duplicate-gamma heads.
// ---------------------------------------------------------------------------
__global__ __launch_bounds__(256) void bcast_kernel(
    const float* __restrict__ gamma, float* __restrict__ out)
{
    const int h = blockIdx.y, b = blockIdx.z;
    const float gh = gamma[h];
    int leader = h;
    for (int h2 = 0; h2 < h; h2++)
        if (gamma[h2] == gh) { leader = h2; break; }
    if (leader == h) return;

    size_t idx = ((size_t)blockIdx.x * 256 + threadIdx.x) * 4;
    const float4 v = *(const float4*)&out[((size_t)(b*Hh + leader)*Ss)*Dd + idx];
    *(float4*)&out[((size_t)(b*Hh + h)*Ss)*Dd + idx] = v;
}

// ---------------------------------------------------------------------------
extern "C" void kernel_launch(void* const* d_in, const int* in_sizes, int n_in,
                              void* d_out, int out_size)
{
    // metadata order: x, e, p, W_q, W_k, W_v, gamma
    const float* e     = (const float*)d_in[1];
    const float* p     = (const float*)d_in[2];
    const float* Wq    = (const float*)d_in[3];
    const float* Wk    = (const float*)d_in[4];
    const float* Wv    = (const float*)d_in[5];
    const float* gamma = (const float*)d_in[6];
    float* out = (float*)d_out;

    static bool init_done = false;
    static void *q2p = nullptr, *k2p = nullptr;
    if (!init_done) {
        cudaFuncSetAttribute(proj_mma_kernel,
                             cudaFuncAttributeMaxDynamicSharedMemorySize, PROJ_SMEM);
        cudaFuncSetAttribute(fused_attn_kernel,
                             cudaFuncAttributeMaxDynamicSharedMemorySize, FUSED_SMEM);
        cudaGetSymbolAddress(&q2p, g_q2);
        cudaGetSymbolAddress(&k2p, g_k2);
        init_done = true;
    }

    cudaMemsetAsync(q2p, 0, NR * sizeof(float));
    cudaMemsetAsync(k2p, 0, NR * sizeof(float));

    dim3 gproj(NR/128, Dd/64, 3);
    proj_mma_kernel<<<gproj, 256, PROJ_SMEM>>>(p, e, Wq, Wk, Wv);

    cudaMemsetAsync(d_out, 0, (size_t)out_size * sizeof(float));

    dim3 gf(16, 16, Bb*Hh);
    fused_attn_kernel<<<gf, 256, FUSED_SMEM>>>(gamma, out);

    dim3 gb((Ss*Dd)/1024, Hh, Bb);
    bcast_kernel<<<gb, 256>>>(gamma, out);
}